// round 8
// baseline (speedup 1.0000x reference)
#include <cuda_runtime.h>
#include <math.h>
#include <stdint.h>

// Problem constants
#define BATCH 4
#define SEQ   2048
#define CMODEL 1024
#define NHEAD 16
#define HDIM  64
#define BH    (BATCH*NHEAD)          // 64
#define MROWS (BATCH*SEQ)            // 8192

// Scratch (allocation-free rule: __device__ globals)
__device__ float g_Q[(size_t)BH*SEQ*HDIM];   // tf32-rounded, pre-scaled by 1/8
__device__ float g_K[(size_t)BH*SEQ*HDIM];   // tf32-rounded
__device__ float g_V[(size_t)BH*SEQ*HDIM];   // tf32-rounded
__device__ float g_A[(size_t)MROWS*CMODEL];  // attention out, fp32

// log2(10000)/64
#define ROPE_L2 0.20762050593060493f

#define KPAD 36   // BK=32 + 4 pad

__device__ __forceinline__ uint32_t f2tf32(float f) {
    uint32_t r;
    asm("cvt.rna.tf32.f32 %0, %1;" : "=r"(r) : "f"(f));
    return r;
}
__device__ __forceinline__ float tf32f(float f) { return __uint_as_float(f2tf32(f)); }

__device__ __forceinline__ void cp16(float* s, const float* g) {
    uint32_t sa = (uint32_t)__cvta_generic_to_shared(s);
    asm volatile("cp.async.cg.shared.global [%0], [%1], 16;\n" :: "r"(sa), "l"(g));
}
#define CP_COMMIT asm volatile("cp.async.commit_group;\n" ::: "memory")
#define CP_WAIT0  asm volatile("cp.async.wait_group 0;\n" ::: "memory")
#define CP_WAIT1  asm volatile("cp.async.wait_group 1;\n" ::: "memory")

__device__ __forceinline__ void mma_tf32(float4& d, const uint32_t* a, const uint32_t* b) {
    asm volatile(
        "mma.sync.aligned.m16n8k8.row.col.f32.tf32.tf32.f32 "
        "{%0,%1,%2,%3}, {%4,%5,%6,%7}, {%8,%9}, {%0,%1,%2,%3};\n"
        : "+f"(d.x), "+f"(d.y), "+f"(d.z), "+f"(d.w)
        : "r"(a[0]), "r"(a[1]), "r"(a[2]), "r"(a[3]), "r"(b[0]), "r"(b[1]));
}

// ---------------------------------------------------------------------------
// GEMM mainloop: C[128x128] tile of A[M][1024] * B[N][1024]^T.
// BK=32 per stage, 2-stage cp.async double buffer (R6 load ordering:
// prefetch issued at loop top, before the wait). Dynamic smem, but stage
// offset is a compile-time stride times (kt&1) -> immediate LDS addressing.
// tf32 cvt at fragment load.
// ---------------------------------------------------------------------------
#define STG_STRIDE (128 * KPAD)   // floats per stage per matrix

#define GSTAGE(B, KT) do {                                                          \
    const float* pa_ = ga + (KT) * 32;                                              \
    const float* pb_ = gb + (KT) * 32;                                              \
    float* da_ = sAw + (B) * STG_STRIDE;                                            \
    float* db_ = sBw + (B) * STG_STRIDE;                                            \
    cp16(da_, pa_);      cp16(da_ + 4,  pa_ + 4);                                   \
    cp16(da_ + 8, pa_ + 8); cp16(da_ + 12, pa_ + 12);                               \
    cp16(db_, pb_);      cp16(db_ + 4,  pb_ + 4);                                   \
    cp16(db_ + 8, pb_ + 8); cp16(db_ + 12, pb_ + 12);                               \
    CP_COMMIT;                                                                      \
} while (0)

#define GEMM_MAINLOOP(APTR, BPTR)                                                   \
    extern __shared__ float smbuf[];                                                \
    float* sA = smbuf;                                                              \
    float* sB = smbuf + 2 * STG_STRIDE;                                             \
    const int tid = threadIdx.x;                                                    \
    const int w = tid >> 5, lane = tid & 31, g = lane >> 2, tg = lane & 3;          \
    const int wm = (w & 1) * 64, wn = (w >> 1) * 32;                                \
    const int m0 = blockIdx.y * 128, n0 = blockIdx.x * 128;                         \
    const int lr = tid >> 1, lc = (tid & 1) * 16;                                   \
    const float* ga = (APTR) + (size_t)(m0 + lr) * CMODEL + lc;                     \
    const float* gb = (BPTR) + (size_t)(n0 + lr) * CMODEL + lc;                     \
    float* sAw = sA + lr * KPAD + lc;                                               \
    float* sBw = sB + lr * KPAD + lc;                                               \
    float4 acc[4][4];                                                               \
    _Pragma("unroll")                                                               \
    for (int i = 0; i < 4; i++)                                                     \
        _Pragma("unroll")                                                           \
        for (int j = 0; j < 4; j++) acc[i][j] = make_float4(0.f, 0.f, 0.f, 0.f);    \
    GSTAGE(0, 0);                                                                   \
    for (int kt = 0; kt < 32; kt++) {                                               \
        if (kt < 31) { GSTAGE((kt + 1) & 1, kt + 1); CP_WAIT1; }                    \
        else         { CP_WAIT0; }                                                  \
        __syncthreads();                                                            \
        const float* sAb = sA + (kt & 1) * STG_STRIDE;                              \
        const float* sBb = sB + (kt & 1) * STG_STRIDE;                              \
        _Pragma("unroll")                                                           \
        for (int ks = 0; ks < 4; ks++) {                                            \
            const int kk = ks * 8;                                                  \
            uint32_t af[4][4], bf[4][2];                                            \
            _Pragma("unroll")                                                       \
            for (int mi = 0; mi < 4; mi++) {                                        \
                const int rbase = wm + mi * 16;                                     \
                af[mi][0] = f2tf32(sAb[(rbase + g) * KPAD + kk + tg]);              \
                af[mi][1] = f2tf32(sAb[(rbase + g + 8) * KPAD + kk + tg]);          \
                af[mi][2] = f2tf32(sAb[(rbase + g) * KPAD + kk + tg + 4]);          \
                af[mi][3] = f2tf32(sAb[(rbase + g + 8) * KPAD + kk + tg + 4]);      \
            }                                                                       \
            _Pragma("unroll")                                                       \
            for (int ni = 0; ni < 4; ni++) {                                        \
                const int cbase = wn + ni * 8;                                      \
                bf[ni][0] = f2tf32(sBb[(cbase + g) * KPAD + kk + tg]);              \
                bf[ni][1] = f2tf32(sBb[(cbase + g) * KPAD + kk + tg + 4]);          \
            }                                                                       \
            _Pragma("unroll")                                                       \
            for (int mi = 0; mi < 4; mi++)                                          \
                _Pragma("unroll")                                                   \
                for (int ni = 0; ni < 4; ni++)                                      \
                    mma_tf32(acc[mi][ni], af[mi], bf[ni]);                          \
        }                                                                           \
        __syncthreads();                                                            \
    }

#define GEMM_SMEM (2 * 2 * STG_STRIDE * 4)   // 73728 bytes

// ---------------------------------------------------------------------------
// Kernel 1: QKV GEMM + bias + RoPE -> g_Q (scaled, tf32), g_K (tf32), g_V (tf32)
// ---------------------------------------------------------------------------
__global__ __launch_bounds__(256) void qkv_gemm_kernel(
    const float* __restrict__ x, const float* __restrict__ wq,
    const float* __restrict__ bias)
{
    GEMM_MAINLOOP(x, wq)

    #pragma unroll
    for (int mi = 0; mi < 4; mi++) {
        #pragma unroll
        for (int ni = 0; ni < 4; ni++) {
            float4 c = acc[mi][ni];
            const int col = n0 + wn + ni * 8 + 2 * tg;   // even
            const int which = col >> 10;                 // 0=q,1=k,2=v
            const int cc = col & 1023;
            const int h = cc >> 6;
            const int d0 = cc & 63;
            const float b0 = bias[col], b1 = bias[col + 1];
            const float invf = exp2f(-(float)d0 * ROPE_L2);
            const int r0 = m0 + wm + mi * 16 + g;
            #pragma unroll
            for (int half = 0; half < 2; half++) {
                const int r = r0 + half * 8;
                float v0 = (half ? c.z : c.x) + b0;
                float v1 = (half ? c.w : c.y) + b1;
                const int b = r >> 11;
                const int t = r & (SEQ - 1);
                const size_t base = ((size_t)(b * NHEAD + h) * SEQ + t) * HDIM + d0;
                if (which == 2) {
                    g_V[base]     = tf32f(v0);
                    g_V[base + 1] = tf32f(v1);
                } else {
                    float s, co;
                    sincosf((float)t * invf, &s, &co);
                    float r0v = v0 * co - v1 * s;
                    float r1v = v0 * s  + v1 * co;
                    if (which == 0) {  // pre-scale Q by 1/sqrt(64)
                        g_Q[base]     = tf32f(r0v * 0.125f);
                        g_Q[base + 1] = tf32f(r1v * 0.125f);
                    } else {
                        g_K[base]     = tf32f(r0v);
                        g_K[base + 1] = tf32f(r1v);
                    }
                }
            }
        }
    }
}

// ---------------------------------------------------------------------------
// Kernel 2: causal flash attention, tf32 mma (unchanged from R6 / 889us run).
// 128 threads (4 warps); Br=64 (16 rows/warp), Bc=32, double-buffered cp.async
// K/V staging; P kept in registers (shuffle permute into A-fragment layout).
// ---------------------------------------------------------------------------
__global__ __launch_bounds__(128, 4) void attn_kernel()
{
    __shared__ float Ks[2][32][68];   // [buf][key][dim]
    __shared__ float Vs[2][32][72];   // [buf][key][dim]

    const int tid = threadIdx.x;
    const int w = tid >> 5, lane = tid & 31, g = lane >> 2, tg = lane & 3;
    const int wq0 = w * 16;
    const int bh = blockIdx.y;
    const int q0 = ((int)gridDim.x - 1 - (int)blockIdx.x) * 64;  // heavy blocks first
    const size_t bhbase = (size_t)bh * SEQ * HDIM;
    const int lr0 = wq0 + g, lr1 = wq0 + g + 8;

#define ATTN_STAGE(B, S0)                                                        \
    {                                                                            \
        _Pragma("unroll")                                                        \
        for (int i = 0; i < 4; i++) {                                            \
            const int idx = tid + i * 128;                                       \
            const int r = idx >> 4, c = (idx & 15) * 4;                          \
            cp16(&Ks[B][r][c], g_K + bhbase + (size_t)((S0) + r) * HDIM + c);    \
            cp16(&Vs[B][r][c], g_V + bhbase + (size_t)((S0) + r) * HDIM + c);    \
        }                                                                        \
        CP_COMMIT;                                                               \
    }

    const int ntiles = q0 / 32 + 2;
    ATTN_STAGE(0, 0)
    ATTN_STAGE(1, 32)

    // Q fragments straight from gmem (already tf32, already scaled)
    uint32_t qf[8][4];
    {
        const float* qb = g_Q + bhbase + (size_t)q0 * HDIM;
        #pragma unroll
        for (int ks = 0; ks < 8; ks++) {
            const int kk = ks * 8;
            qf[ks][0] = __float_as_uint(qb[(size_t)lr0 * HDIM + kk + tg]);
            qf[ks][1] = __float_as_uint(qb[(size_t)lr1 * HDIM + kk + tg]);
            qf[ks][2] = __float_as_uint(qb[(size_t)lr0 * HDIM + kk + tg + 4]);
            qf[ks][3] = __float_as_uint(qb[(size_t)lr1 * HDIM + kk + tg + 4]);
        }
    }

    float4 o[8];
    #pragma unroll
    for (int ni = 0; ni < 8; ni++) o[ni] = make_float4(0.f, 0.f, 0.f, 0.f);
    float m0r = -1e30f, m1r = -1e30f, l0 = 0.f, l1 = 0.f;

    for (int it = 0; it < ntiles; it++) {
        const int s0 = it * 32;
        if (it + 1 < ntiles) { CP_WAIT1; } else { CP_WAIT0; }
        __syncthreads();
        const int b = it & 1;

        // ---- S = Q * K^T (64 warp rows x 32 keys) ----
        float4 s[4];
        #pragma unroll
        for (int ni = 0; ni < 4; ni++) s[ni] = make_float4(0.f, 0.f, 0.f, 0.f);
        #pragma unroll
        for (int ks = 0; ks < 8; ks++) {
            const int kk = ks * 8;
            #pragma unroll
            for (int ni = 0; ni < 4; ni++) {
                uint32_t bfr[2];
                bfr[0] = __float_as_uint(Ks[b][ni * 8 + g][kk + tg]);
                bfr[1] = __float_as_uint(Ks[b][ni * 8 + g][kk + tg + 4]);
                mma_tf32(s[ni], qf[ks], bfr);
            }
        }

        // ---- causal mask (only tiles that can cross the diagonal) ----
        if (s0 + 31 > q0) {
            #pragma unroll
            for (int ni = 0; ni < 4; ni++) {
                const int c0 = s0 + ni * 8 + 2 * tg, c1 = c0 + 1;
                const int t0 = q0 + lr0, t1 = q0 + lr1;
                if (c0 > t0) s[ni].x = -1e30f;
                if (c1 > t0) s[ni].y = -1e30f;
                if (c0 > t1) s[ni].z = -1e30f;
                if (c1 > t1) s[ni].w = -1e30f;
            }
        }

        // ---- online softmax ----
        float tm0 = -1e30f, tm1 = -1e30f;
        #pragma unroll
        for (int ni = 0; ni < 4; ni++) {
            tm0 = fmaxf(tm0, fmaxf(s[ni].x, s[ni].y));
            tm1 = fmaxf(tm1, fmaxf(s[ni].z, s[ni].w));
        }
        tm0 = fmaxf(tm0, __shfl_xor_sync(0xffffffffu, tm0, 1));
        tm0 = fmaxf(tm0, __shfl_xor_sync(0xffffffffu, tm0, 2));
        tm1 = fmaxf(tm1, __shfl_xor_sync(0xffffffffu, tm1, 1));
        tm1 = fmaxf(tm1, __shfl_xor_sync(0xffffffffu, tm1, 2));

        const float mn0 = fmaxf(m0r, tm0), mn1 = fmaxf(m1r, tm1);
        const float cr0 = __expf(m0r - mn0), cr1 = __expf(m1r - mn1);
        m0r = mn0; m1r = mn1;

        float ls0 = 0.f, ls1 = 0.f;
        #pragma unroll
        for (int ni = 0; ni < 4; ni++) {
            s[ni].x = __expf(s[ni].x - mn0);
            s[ni].y = __expf(s[ni].y - mn0);
            s[ni].z = __expf(s[ni].z - mn1);
            s[ni].w = __expf(s[ni].w - mn1);
            ls0 += s[ni].x + s[ni].y;
            ls1 += s[ni].z + s[ni].w;
        }
        ls0 += __shfl_xor_sync(0xffffffffu, ls0, 1);
        ls0 += __shfl_xor_sync(0xffffffffu, ls0, 2);
        ls1 += __shfl_xor_sync(0xffffffffu, ls1, 1);
        ls1 += __shfl_xor_sync(0xffffffffu, ls1, 2);
        l0 = l0 * cr0 + ls0;
        l1 = l1 * cr1 + ls1;

        #pragma unroll
        for (int ni = 0; ni < 8; ni++) {
            o[ni].x *= cr0; o[ni].y *= cr0;
            o[ni].z *= cr1; o[ni].w *= cr1;
        }

        // ---- P (registers) -> A-fragment layout via shuffles; O += P * V ----
        uint32_t px[4], py[4], pz[4], pw[4];
        #pragma unroll
        for (int ni = 0; ni < 4; ni++) {
            px[ni] = f2tf32(s[ni].x); py[ni] = f2tf32(s[ni].y);
            pz[ni] = f2tf32(s[ni].z); pw[ni] = f2tf32(s[ni].w);
        }
        const int src0 = (lane & ~3) | (tg >> 1);
        const int src1 = src0 + 2;
        #pragma unroll
        for (int ks2 = 0; ks2 < 4; ks2++) {
            const uint32_t x0 = __shfl_sync(0xffffffffu, px[ks2], src0);
            const uint32_t y0 = __shfl_sync(0xffffffffu, py[ks2], src0);
            const uint32_t z0 = __shfl_sync(0xffffffffu, pz[ks2], src0);
            const uint32_t w0 = __shfl_sync(0xffffffffu, pw[ks2], src0);
            const uint32_t x1 = __shfl_sync(0xffffffffu, px[ks2], src1);
            const uint32_t y1 = __shfl_sync(0xffffffffu, py[ks2], src1);
            const uint32_t z1 = __shfl_sync(0xffffffffu, pz[ks2], src1);
            const uint32_t w1 = __shfl_sync(0xffffffffu, pw[ks2], src1);
            uint32_t af[4];
            af[0] = (tg & 1) ? y0 : x0;
            af[1] = (tg & 1) ? w0 : z0;
            af[2] = (tg & 1) ? y1 : x1;
            af[3] = (tg & 1) ? w1 : z1;
            const int kk = ks2 * 8;
            #pragma unroll
            for (int ni = 0; ni < 8; ni++) {
                uint32_t bfr[2];
                bfr[0] = __float_as_uint(Vs[b][kk + tg][ni * 8 + g]);
                bfr[1] = __float_as_uint(Vs[b][kk + tg + 4][ni * 8 + g]);
                mma_tf32(o[ni], af, bfr);
            }
        }

        __syncthreads();
        if (it + 2 < ntiles) ATTN_STAGE(it & 1, s0 + 64)
    }

    // ---- epilogue: normalize and write to g_A ----
    const float inv0 = 1.f / l0, inv1 = 1.f / l1;
    const int b2 = bh >> 4, h = bh & 15;
    const int t0 = q0 + lr0, t1 = q0 + lr1;
    float* d0p = g_A + ((size_t)(b2 * SEQ + t0)) * CMODEL + h * HDIM;
    float* d1p = g_A + ((size_t)(b2 * SEQ + t1)) * CMODEL + h * HDIM;
    #pragma unroll
    for (int ni = 0; ni < 8; ni++) {
        const int c0 = ni * 8 + 2 * tg;
        d0p[c0]     = o[ni].x * inv0;
        d0p[c0 + 1] = o[ni].y * inv0;
        d1p[c0]     = o[ni].z * inv1;
        d1p[c0 + 1] = o[ni].w * inv1;
    }
#undef ATTN_STAGE
}

// ---------------------------------------------------------------------------
// Kernel 3: output projection + bias -> d_out
// ---------------------------------------------------------------------------
__global__ __launch_bounds__(256) void proj_gemm_kernel(
    const float* __restrict__ wo, const float* __restrict__ bias,
    float* __restrict__ out)
{
    GEMM_MAINLOOP(g_A, wo)

    #pragma unroll
    for (int mi = 0; mi < 4; mi++) {
        #pragma unroll
        for (int ni = 0; ni < 4; ni++) {
            float4 c = acc[mi][ni];
            const int col = n0 + wn + ni * 8 + 2 * tg;
            const float b0 = bias[col], b1 = bias[col + 1];
            const int r0 = m0 + wm + mi * 16 + g;
            out[(size_t)r0 * CMODEL + col]           = c.x + b0;
            out[(size_t)r0 * CMODEL + col + 1]       = c.y + b1;
            out[(size_t)(r0 + 8) * CMODEL + col]     = c.z + b0;
            out[(size_t)(r0 + 8) * CMODEL + col + 1] = c.w + b1;
        }
    }
}

// ---------------------------------------------------------------------------
extern "C" void kernel_launch(void* const* d_in, const int* in_sizes, int n_in,
                              void* d_out, int out_size)
{
    const float* x      = (const float*)d_in[0];
    const float* qkv_w  = (const float*)d_in[1];
    const float* qkv_b  = (const float*)d_in[2];
    const float* out_w  = (const float*)d_in[3];
    const float* out_b  = (const float*)d_in[4];
    float* out = (float*)d_out;

    cudaFuncSetAttribute(qkv_gemm_kernel, cudaFuncAttributeMaxDynamicSharedMemorySize, GEMM_SMEM);
    cudaFuncSetAttribute(proj_gemm_kernel, cudaFuncAttributeMaxDynamicSharedMemorySize, GEMM_SMEM);

    qkv_gemm_kernel<<<dim3(3*CMODEL/128, MROWS/128), 256, GEMM_SMEM>>>(x, qkv_w, qkv_b);
    attn_kernel<<<dim3(SEQ/64, BH), 128>>>();
    proj_gemm_kernel<<<dim3(CMODEL/128, MROWS/128), 256, GEMM_SMEM>>>(out_w, out_b, out);
}

// round 9
// speedup vs baseline: 1.0817x; 1.0817x over previous
#include <cuda_runtime.h>
#include <math.h>
#include <stdint.h>

// Problem constants
#define BATCH 4
#define SEQ   2048
#define CMODEL 1024
#define NHEAD 16
#define HDIM  64
#define BH    (BATCH*NHEAD)          // 64
#define MROWS (BATCH*SEQ)            // 8192

// Scratch (allocation-free rule: __device__ globals)
__device__ float g_Q[(size_t)BH*SEQ*HDIM];   // tf32-rounded, pre-scaled by 1/8
__device__ float g_K[(size_t)BH*SEQ*HDIM];   // tf32-rounded
__device__ float g_V[(size_t)BH*SEQ*HDIM];   // tf32-rounded
__device__ float g_A[(size_t)MROWS*CMODEL];  // attention out, tf32-rounded
__device__ float g_Xr[(size_t)MROWS*CMODEL];      // x, tf32-rounded
__device__ float g_Wqkv[(size_t)3*CMODEL*CMODEL]; // qkv_w, tf32-rounded
__device__ float g_Wo[(size_t)CMODEL*CMODEL];     // out_w, tf32-rounded

// log2(10000)/64
#define ROPE_L2 0.20762050593060493f

#define KPAD 20   // k-stride in shared (16 used + 4 pad)

__device__ __forceinline__ uint32_t f2tf32(float f) {
    uint32_t r;
    asm("cvt.rna.tf32.f32 %0, %1;" : "=r"(r) : "f"(f));
    return r;
}
__device__ __forceinline__ float tf32f(float f) { return __uint_as_float(f2tf32(f)); }

__device__ __forceinline__ void cp16(float* s, const float* g) {
    uint32_t sa = (uint32_t)__cvta_generic_to_shared(s);
    asm volatile("cp.async.cg.shared.global [%0], [%1], 16;\n" :: "r"(sa), "l"(g));
}
#define CP_COMMIT asm volatile("cp.async.commit_group;\n" ::: "memory")
#define CP_WAIT0  asm volatile("cp.async.wait_group 0;\n" ::: "memory")
#define CP_WAIT1  asm volatile("cp.async.wait_group 1;\n" ::: "memory")

__device__ __forceinline__ void mma_tf32(float4& d, const uint32_t* a, const uint32_t* b) {
    asm volatile(
        "mma.sync.aligned.m16n8k8.row.col.f32.tf32.tf32.f32 "
        "{%0,%1,%2,%3}, {%4,%5,%6,%7}, {%8,%9}, {%0,%1,%2,%3};\n"
        : "+f"(d.x), "+f"(d.y), "+f"(d.z), "+f"(d.w)
        : "r"(a[0]), "r"(a[1]), "r"(a[2]), "r"(a[3]), "r"(b[0]), "r"(b[1]));
}

// ---------------------------------------------------------------------------
// Kernel 0: tf32 pre-round (float4 vectorized)
// ---------------------------------------------------------------------------
__global__ __launch_bounds__(256) void round_kernel(
    const float4* __restrict__ in, float4* __restrict__ outp, int n4)
{
    const int i = blockIdx.x * 256 + threadIdx.x;
    if (i < n4) {
        float4 v = in[i];
        float4 o;
        o.x = tf32f(v.x); o.y = tf32f(v.y); o.z = tf32f(v.z); o.w = tf32f(v.w);
        outp[i] = o;
    }
}

// ---------------------------------------------------------------------------
// GEMM mainloop (EXACT R6 structure: static smem, BK=16, 2-stage cp.async,
// prefetch issued before wait, 2 barriers/tile). Only change vs R6:
// fragment loads are raw bits (inputs pre-rounded to tf32).
// ---------------------------------------------------------------------------
#define GEMM_MAINLOOP(APTR, BPTR)                                                   \
    __shared__ float As[2][128][KPAD];                                              \
    __shared__ float Bs[2][128][KPAD];                                              \
    const int tid = threadIdx.x;                                                    \
    const int w = tid >> 5, lane = tid & 31, g = lane >> 2, tg = lane & 3;          \
    const int wm = (w & 1) * 64, wn = (w >> 1) * 32;                                \
    const int m0 = blockIdx.y * 128, n0 = blockIdx.x * 128;                         \
    const int lr = tid >> 1, lc = (tid & 1) * 8;                                    \
    const float* ga = (APTR) + (size_t)(m0 + lr) * CMODEL + lc;                     \
    const float* gb = (BPTR) + (size_t)(n0 + lr) * CMODEL + lc;                     \
    float4 acc[4][4];                                                               \
    _Pragma("unroll")                                                               \
    for (int i = 0; i < 4; i++)                                                     \
        _Pragma("unroll")                                                           \
        for (int j = 0; j < 4; j++) acc[i][j] = make_float4(0.f, 0.f, 0.f, 0.f);    \
    cp16(&As[0][lr][lc], ga); cp16(&As[0][lr][lc + 4], ga + 4);                     \
    cp16(&Bs[0][lr][lc], gb); cp16(&Bs[0][lr][lc + 4], gb + 4);                     \
    CP_COMMIT;                                                                      \
    for (int kt = 0; kt < CMODEL / 16; kt++) {                                      \
        if (kt < CMODEL / 16 - 1) {                                                 \
            const float* pa = ga + (kt + 1) * 16;                                   \
            const float* pb = gb + (kt + 1) * 16;                                   \
            float* sa = &As[(kt + 1) & 1][lr][lc];                                  \
            float* sb = &Bs[(kt + 1) & 1][lr][lc];                                  \
            cp16(sa, pa); cp16(sa + 4, pa + 4);                                     \
            cp16(sb, pb); cp16(sb + 4, pb + 4);                                     \
            CP_COMMIT; CP_WAIT1;                                                    \
        } else { CP_WAIT0; }                                                        \
        __syncthreads();                                                            \
        const int buf = kt & 1;                                                     \
        _Pragma("unroll")                                                           \
        for (int ks = 0; ks < 2; ks++) {                                            \
            const int kk = ks * 8;                                                  \
            uint32_t af[4][4], bf[4][2];                                            \
            _Pragma("unroll")                                                       \
            for (int mi = 0; mi < 4; mi++) {                                        \
                const int rbase = wm + mi * 16;                                     \
                af[mi][0] = __float_as_uint(As[buf][rbase + g][kk + tg]);           \
                af[mi][1] = __float_as_uint(As[buf][rbase + g + 8][kk + tg]);       \
                af[mi][2] = __float_as_uint(As[buf][rbase + g][kk + tg + 4]);       \
                af[mi][3] = __float_as_uint(As[buf][rbase + g + 8][kk + tg + 4]);   \
            }                                                                       \
            _Pragma("unroll")                                                       \
            for (int ni = 0; ni < 4; ni++) {                                        \
                const int cbase = wn + ni * 8;                                      \
                bf[ni][0] = __float_as_uint(Bs[buf][cbase + g][kk + tg]);           \
                bf[ni][1] = __float_as_uint(Bs[buf][cbase + g][kk + tg + 4]);       \
            }                                                                       \
            _Pragma("unroll")                                                       \
            for (int mi = 0; mi < 4; mi++)                                          \
                _Pragma("unroll")                                                   \
                for (int ni = 0; ni < 4; ni++)                                      \
                    mma_tf32(acc[mi][ni], af[mi], bf[ni]);                          \
        }                                                                           \
        __syncthreads();                                                            \
    }

// ---------------------------------------------------------------------------
// Kernel 1: QKV GEMM + bias + RoPE -> g_Q (scaled, tf32), g_K (tf32), g_V (tf32)
// ---------------------------------------------------------------------------
__global__ __launch_bounds__(256) void qkv_gemm_kernel(
    const float* __restrict__ xr, const float* __restrict__ wq,
    const float* __restrict__ bias)
{
    GEMM_MAINLOOP(xr, wq)

    #pragma unroll
    for (int mi = 0; mi < 4; mi++) {
        #pragma unroll
        for (int ni = 0; ni < 4; ni++) {
            float4 c = acc[mi][ni];
            const int col = n0 + wn + ni * 8 + 2 * tg;   // even
            const int which = col >> 10;                 // 0=q,1=k,2=v
            const int cc = col & 1023;
            const int h = cc >> 6;
            const int d0 = cc & 63;
            const float b0 = bias[col], b1 = bias[col + 1];
            const float invf = exp2f(-(float)d0 * ROPE_L2);
            const int r0 = m0 + wm + mi * 16 + g;
            #pragma unroll
            for (int half = 0; half < 2; half++) {
                const int r = r0 + half * 8;
                float v0 = (half ? c.z : c.x) + b0;
                float v1 = (half ? c.w : c.y) + b1;
                const int b = r >> 11;
                const int t = r & (SEQ - 1);
                const size_t base = ((size_t)(b * NHEAD + h) * SEQ + t) * HDIM + d0;
                if (which == 2) {
                    g_V[base]     = tf32f(v0);
                    g_V[base + 1] = tf32f(v1);
                } else {
                    float s, co;
                    sincosf((float)t * invf, &s, &co);
                    float r0v = v0 * co - v1 * s;
                    float r1v = v0 * s  + v1 * co;
                    if (which == 0) {  // pre-scale Q by 1/sqrt(64)
                        g_Q[base]     = tf32f(r0v * 0.125f);
                        g_Q[base + 1] = tf32f(r1v * 0.125f);
                    } else {
                        g_K[base]     = tf32f(r0v);
                        g_K[base + 1] = tf32f(r1v);
                    }
                }
            }
        }
    }
}

// ---------------------------------------------------------------------------
// Kernel 2: causal flash attention, tf32 mma (R6 version; epilogue now
// writes tf32-rounded g_A so proj can use raw-bit frag loads).
// ---------------------------------------------------------------------------
__global__ __launch_bounds__(128, 4) void attn_kernel()
{
    __shared__ float Ks[2][32][68];   // [buf][key][dim]
    __shared__ float Vs[2][32][72];   // [buf][key][dim]

    const int tid = threadIdx.x;
    const int w = tid >> 5, lane = tid & 31, g = lane >> 2, tg = lane & 3;
    const int wq0 = w * 16;
    const int bh = blockIdx.y;
    const int q0 = ((int)gridDim.x - 1 - (int)blockIdx.x) * 64;  // heavy blocks first
    const size_t bhbase = (size_t)bh * SEQ * HDIM;
    const int lr0 = wq0 + g, lr1 = wq0 + g + 8;

#define ATTN_STAGE(B, S0)                                                        \
    {                                                                            \
        _Pragma("unroll")                                                        \
        for (int i = 0; i < 4; i++) {                                            \
            const int idx = tid + i * 128;                                       \
            const int r = idx >> 4, c = (idx & 15) * 4;                          \
            cp16(&Ks[B][r][c], g_K + bhbase + (size_t)((S0) + r) * HDIM + c);    \
            cp16(&Vs[B][r][c], g_V + bhbase + (size_t)((S0) + r) * HDIM + c);    \
        }                                                                        \
        CP_COMMIT;                                                               \
    }

    const int ntiles = q0 / 32 + 2;
    ATTN_STAGE(0, 0)
    ATTN_STAGE(1, 32)

    // Q fragments straight from gmem (already tf32, already scaled)
    uint32_t qf[8][4];
    {
        const float* qb = g_Q + bhbase + (size_t)q0 * HDIM;
        #pragma unroll
        for (int ks = 0; ks < 8; ks++) {
            const int kk = ks * 8;
            qf[ks][0] = __float_as_uint(qb[(size_t)lr0 * HDIM + kk + tg]);
            qf[ks][1] = __float_as_uint(qb[(size_t)lr1 * HDIM + kk + tg]);
            qf[ks][2] = __float_as_uint(qb[(size_t)lr0 * HDIM + kk + tg + 4]);
            qf[ks][3] = __float_as_uint(qb[(size_t)lr1 * HDIM + kk + tg + 4]);
        }
    }

    float4 o[8];
    #pragma unroll
    for (int ni = 0; ni < 8; ni++) o[ni] = make_float4(0.f, 0.f, 0.f, 0.f);
    float m0r = -1e30f, m1r = -1e30f, l0 = 0.f, l1 = 0.f;

    for (int it = 0; it < ntiles; it++) {
        const int s0 = it * 32;
        if (it + 1 < ntiles) { CP_WAIT1; } else { CP_WAIT0; }
        __syncthreads();
        const int b = it & 1;

        // ---- S = Q * K^T (64 warp rows x 32 keys) ----
        float4 s[4];
        #pragma unroll
        for (int ni = 0; ni < 4; ni++) s[ni] = make_float4(0.f, 0.f, 0.f, 0.f);
        #pragma unroll
        for (int ks = 0; ks < 8; ks++) {
            const int kk = ks * 8;
            #pragma unroll
            for (int ni = 0; ni < 4; ni++) {
                uint32_t bfr[2];
                bfr[0] = __float_as_uint(Ks[b][ni * 8 + g][kk + tg]);
                bfr[1] = __float_as_uint(Ks[b][ni * 8 + g][kk + tg + 4]);
                mma_tf32(s[ni], qf[ks], bfr);
            }
        }

        // ---- causal mask (only tiles that can cross the diagonal) ----
        if (s0 + 31 > q0) {
            #pragma unroll
            for (int ni = 0; ni < 4; ni++) {
                const int c0 = s0 + ni * 8 + 2 * tg, c1 = c0 + 1;
                const int t0 = q0 + lr0, t1 = q0 + lr1;
                if (c0 > t0) s[ni].x = -1e30f;
                if (c1 > t0) s[ni].y = -1e30f;
                if (c0 > t1) s[ni].z = -1e30f;
                if (c1 > t1) s[ni].w = -1e30f;
            }
        }

        // ---- online softmax ----
        float tm0 = -1e30f, tm1 = -1e30f;
        #pragma unroll
        for (int ni = 0; ni < 4; ni++) {
            tm0 = fmaxf(tm0, fmaxf(s[ni].x, s[ni].y));
            tm1 = fmaxf(tm1, fmaxf(s[ni].z, s[ni].w));
        }
        tm0 = fmaxf(tm0, __shfl_xor_sync(0xffffffffu, tm0, 1));
        tm0 = fmaxf(tm0, __shfl_xor_sync(0xffffffffu, tm0, 2));
        tm1 = fmaxf(tm1, __shfl_xor_sync(0xffffffffu, tm1, 1));
        tm1 = fmaxf(tm1, __shfl_xor_sync(0xffffffffu, tm1, 2));

        const float mn0 = fmaxf(m0r, tm0), mn1 = fmaxf(m1r, tm1);
        const float cr0 = __expf(m0r - mn0), cr1 = __expf(m1r - mn1);
        m0r = mn0; m1r = mn1;

        float ls0 = 0.f, ls1 = 0.f;
        #pragma unroll
        for (int ni = 0; ni < 4; ni++) {
            s[ni].x = __expf(s[ni].x - mn0);
            s[ni].y = __expf(s[ni].y - mn0);
            s[ni].z = __expf(s[ni].z - mn1);
            s[ni].w = __expf(s[ni].w - mn1);
            ls0 += s[ni].x + s[ni].y;
            ls1 += s[ni].z + s[ni].w;
        }
        ls0 += __shfl_xor_sync(0xffffffffu, ls0, 1);
        ls0 += __shfl_xor_sync(0xffffffffu, ls0, 2);
        ls1 += __shfl_xor_sync(0xffffffffu, ls1, 1);
        ls1 += __shfl_xor_sync(0xffffffffu, ls1, 2);
        l0 = l0 * cr0 + ls0;
        l1 = l1 * cr1 + ls1;

        #pragma unroll
        for (int ni = 0; ni < 8; ni++) {
            o[ni].x *= cr0; o[ni].y *= cr0;
            o[ni].z *= cr1; o[ni].w *= cr1;
        }

        // ---- P (registers) -> A-fragment layout via shuffles; O += P * V ----
        uint32_t px[4], py[4], pz[4], pw[4];
        #pragma unroll
        for (int ni = 0; ni < 4; ni++) {
            px[ni] = f2tf32(s[ni].x); py[ni] = f2tf32(s[ni].y);
            pz[ni] = f2tf32(s[ni].z); pw[ni] = f2tf32(s[ni].w);
        }
        const int src0 = (lane & ~3) | (tg >> 1);
        const int src1 = src0 + 2;
        #pragma unroll
        for (int ks2 = 0; ks2 < 4; ks2++) {
            const uint32_t x0 = __shfl_sync(0xffffffffu, px[ks2], src0);
            const uint32_t y0 = __shfl_sync(0xffffffffu, py[ks2], src0);
            const uint32_t z0 = __shfl_sync(0xffffffffu, pz[ks2], src0);
            const uint32_t w0 = __shfl_sync(0xffffffffu, pw[ks2], src0);
            const uint32_t x1 = __shfl_sync(0xffffffffu, px[ks2], src1);
            const uint32_t y1 = __shfl_sync(0xffffffffu, py[ks2], src1);
            const uint32_t z1 = __shfl_sync(0xffffffffu, pz[ks2], src1);
            const uint32_t w1 = __shfl_sync(0xffffffffu, pw[ks2], src1);
            uint32_t af[4];
            af[0] = (tg & 1) ? y0 : x0;
            af[1] = (tg & 1) ? w0 : z0;
            af[2] = (tg & 1) ? y1 : x1;
            af[3] = (tg & 1) ? w1 : z1;
            const int kk = ks2 * 8;
            #pragma unroll
            for (int ni = 0; ni < 8; ni++) {
                uint32_t bfr[2];
                bfr[0] = __float_as_uint(Vs[b][kk + tg][ni * 8 + g]);
                bfr[1] = __float_as_uint(Vs[b][kk + tg + 4][ni * 8 + g]);
                mma_tf32(o[ni], af, bfr);
            }
        }

        __syncthreads();
        if (it + 2 < ntiles) ATTN_STAGE(it & 1, s0 + 64)
    }

    // ---- epilogue: normalize, tf32-round, write to g_A ----
    const float inv0 = 1.f / l0, inv1 = 1.f / l1;
    const int b2 = bh >> 4, h = bh & 15;
    const int t0 = q0 + lr0, t1 = q0 + lr1;
    float* d0p = g_A + ((size_t)(b2 * SEQ + t0)) * CMODEL + h * HDIM;
    float* d1p = g_A + ((size_t)(b2 * SEQ + t1)) * CMODEL + h * HDIM;
    #pragma unroll
    for (int ni = 0; ni < 8; ni++) {
        const int c0 = ni * 8 + 2 * tg;
        d0p[c0]     = tf32f(o[ni].x * inv0);
        d0p[c0 + 1] = tf32f(o[ni].y * inv0);
        d1p[c0]     = tf32f(o[ni].z * inv1);
        d1p[c0 + 1] = tf32f(o[ni].w * inv1);
    }
#undef ATTN_STAGE
}

// ---------------------------------------------------------------------------
// Kernel 3: output projection + bias -> d_out
// ---------------------------------------------------------------------------
__global__ __launch_bounds__(256) void proj_gemm_kernel(
    const float* __restrict__ wo, const float* __restrict__ bias,
    float* __restrict__ out)
{
    GEMM_MAINLOOP(g_A, wo)

    #pragma unroll
    for (int mi = 0; mi < 4; mi++) {
        #pragma unroll
        for (int ni = 0; ni < 4; ni++) {
            float4 c = acc[mi][ni];
            const int col = n0 + wn + ni * 8 + 2 * tg;
            const float b0 = bias[col], b1 = bias[col + 1];
            const int r0 = m0 + wm + mi * 16 + g;
            out[(size_t)r0 * CMODEL + col]           = c.x + b0;
            out[(size_t)r0 * CMODEL + col + 1]       = c.y + b1;
            out[(size_t)(r0 + 8) * CMODEL + col]     = c.z + b0;
            out[(size_t)(r0 + 8) * CMODEL + col + 1] = c.w + b1;
        }
    }
}

// ---------------------------------------------------------------------------
extern "C" void kernel_launch(void* const* d_in, const int* in_sizes, int n_in,
                              void* d_out, int out_size)
{
    const float* x      = (const float*)d_in[0];
    const float* qkv_w  = (const float*)d_in[1];
    const float* qkv_b  = (const float*)d_in[2];
    const float* out_w  = (const float*)d_in[3];
    const float* out_b  = (const float*)d_in[4];
    float* out = (float*)d_out;

    float* xr; cudaGetSymbolAddress((void**)&xr, g_Xr);
    float* wq; cudaGetSymbolAddress((void**)&wq, g_Wqkv);
    float* wo; cudaGetSymbolAddress((void**)&wo, g_Wo);

    // tf32 pre-round of GEMM operands
    {
        const int n4x = MROWS * CMODEL / 4;          // 2097152
        const int n4q = 3 * CMODEL * CMODEL / 4;     // 786432
        const int n4o = CMODEL * CMODEL / 4;         // 262144
        round_kernel<<<(n4x + 255) / 256, 256>>>((const float4*)x, (float4*)xr, n4x);
        round_kernel<<<(n4q + 255) / 256, 256>>>((const float4*)qkv_w, (float4*)wq, n4q);
        round_kernel<<<(n4o + 255) / 256, 256>>>((const float4*)out_w, (float4*)wo, n4o);
    }

    qkv_gemm_kernel<<<dim3(3*CMODEL/128, MROWS/128), 256>>>(xr, wq, qkv_b);
    attn_kernel<<<dim3(SEQ/64, BH), 128>>>();
    proj_gemm_kernel<<<dim3(CMODEL/128, MROWS/128), 256>>>(wo, out_b, out);
}

// round 10
// speedup vs baseline: 1.9101x; 1.7658x over previous
#include <cuda_runtime.h>
#include <cuda_fp16.h>
#include <math.h>
#include <stdint.h>

// Problem constants
#define BATCH 4
#define SEQ   2048
#define CMODEL 1024
#define NHEAD 16
#define HDIM  64
#define BH    (BATCH*NHEAD)          // 64
#define MROWS (BATCH*SEQ)            // 8192

// Scratch (allocation-free rule: __device__ globals)
__device__ __half g_Q[(size_t)BH*SEQ*HDIM];    // [bh][t][d], pre-scaled by 1/8
__device__ __half g_K[(size_t)BH*SEQ*HDIM];    // [bh][t][d]
__device__ __half g_Vt[(size_t)BH*HDIM*SEQ];   // [bh][d][t]  (transposed!)
__device__ __half g_A[(size_t)MROWS*CMODEL];   // attention out (proj input)
__device__ __half g_Xh[(size_t)MROWS*CMODEL];      // x in fp16
__device__ __half g_Wh[(size_t)3*CMODEL*CMODEL];   // qkv_w in fp16
__device__ __half g_Woh[(size_t)CMODEL*CMODEL];    // out_w in fp16

// log2(10000)/64
#define ROPE_L2 0.20762050593060493f

#define KPAD 40    // GEMM: halves per smem row (32 used + 8 pad) -> conflict-free
#define KSPAD 72   // attn K tile: 64 + 8
#define VSPAD 40   // attn V tile: 32 + 8

__device__ __forceinline__ void cp16(void* s, const void* g) {
    uint32_t sa = (uint32_t)__cvta_generic_to_shared(s);
    asm volatile("cp.async.cg.shared.global [%0], [%1], 16;\n" :: "r"(sa), "l"(g));
}
#define CP_COMMIT asm volatile("cp.async.commit_group;\n" ::: "memory")
#define CP_WAIT0  asm volatile("cp.async.wait_group 0;\n" ::: "memory")
#define CP_WAIT1  asm volatile("cp.async.wait_group 1;\n" ::: "memory")

#define U32(p) (*(const uint32_t*)(p))

__device__ __forceinline__ uint32_t packh2(float lo, float hi) {
    __half2 h = __floats2half2_rn(lo, hi);
    return *(uint32_t*)&h;
}

__device__ __forceinline__ void mma_f16(float4& d, const uint32_t* a, const uint32_t* b) {
    asm volatile(
        "mma.sync.aligned.m16n8k16.row.col.f32.f16.f16.f32 "
        "{%0,%1,%2,%3}, {%4,%5,%6,%7}, {%8,%9}, {%0,%1,%2,%3};\n"
        : "+f"(d.x), "+f"(d.y), "+f"(d.z), "+f"(d.w)
        : "r"(a[0]), "r"(a[1]), "r"(a[2]), "r"(a[3]), "r"(b[0]), "r"(b[1]));
}

// ---------------------------------------------------------------------------
// Kernel 0: fp32 -> fp16 convert (vectorized)
// ---------------------------------------------------------------------------
__global__ __launch_bounds__(256) void cvt_half_kernel(
    const float4* __restrict__ in, uint2* __restrict__ outp, int n4)
{
    const int i = blockIdx.x * 256 + threadIdx.x;
    if (i < n4) {
        float4 v = in[i];
        uint2 o;
        o.x = packh2(v.x, v.y);
        o.y = packh2(v.z, v.w);
        outp[i] = o;
    }
}

// ---------------------------------------------------------------------------
// GEMM mainloop: C[128x128] tile of A[M][1024](half) * B[N][1024](half)^T.
// R6 structure: static smem, 2-stage cp.async, prefetch-before-wait,
// 2 barriers/tile. BK=32 halves, 2x m16n8k16 k-steps per tile, 32 tiles.
// 8 warps 2(M)x4(N); warp tile 64x32.
// ---------------------------------------------------------------------------
#define GEMM_MAINLOOP(APTR, BPTR)                                                   \
    __shared__ __half As[2][128][KPAD];                                             \
    __shared__ __half Bs[2][128][KPAD];                                             \
    const int tid = threadIdx.x;                                                    \
    const int w = tid >> 5, lane = tid & 31, g = lane >> 2, tg = lane & 3;          \
    const int wm = (w & 1) * 64, wn = (w >> 1) * 32;                                \
    const int m0 = blockIdx.y * 128, n0 = blockIdx.x * 128;                         \
    const int lr = tid >> 1, lc = (tid & 1) * 16;                                   \
    const __half* ga = (APTR) + (size_t)(m0 + lr) * CMODEL + lc;                    \
    const __half* gb = (BPTR) + (size_t)(n0 + lr) * CMODEL + lc;                    \
    float4 acc[4][4];                                                               \
    _Pragma("unroll")                                                               \
    for (int i = 0; i < 4; i++)                                                     \
        _Pragma("unroll")                                                           \
        for (int j = 0; j < 4; j++) acc[i][j] = make_float4(0.f, 0.f, 0.f, 0.f);    \
    cp16(&As[0][lr][lc], ga); cp16(&As[0][lr][lc + 8], ga + 8);                     \
    cp16(&Bs[0][lr][lc], gb); cp16(&Bs[0][lr][lc + 8], gb + 8);                     \
    CP_COMMIT;                                                                      \
    for (int kt = 0; kt < 32; kt++) {                                               \
        if (kt < 31) {                                                              \
            const __half* pa = ga + (kt + 1) * 32;                                  \
            const __half* pb = gb + (kt + 1) * 32;                                  \
            __half* sa = &As[(kt + 1) & 1][lr][lc];                                 \
            __half* sb = &Bs[(kt + 1) & 1][lr][lc];                                 \
            cp16(sa, pa); cp16(sa + 8, pa + 8);                                     \
            cp16(sb, pb); cp16(sb + 8, pb + 8);                                     \
            CP_COMMIT; CP_WAIT1;                                                    \
        } else { CP_WAIT0; }                                                        \
        __syncthreads();                                                            \
        const int buf = kt & 1;                                                     \
        _Pragma("unroll")                                                           \
        for (int ks = 0; ks < 2; ks++) {                                            \
            const int kk = ks * 16;                                                 \
            uint32_t af[4][4], bf[4][2];                                            \
            _Pragma("unroll")                                                       \
            for (int mi = 0; mi < 4; mi++) {                                        \
                const int rbase = wm + mi * 16;                                     \
                af[mi][0] = U32(&As[buf][rbase + g][kk + 2*tg]);                    \
                af[mi][1] = U32(&As[buf][rbase + g + 8][kk + 2*tg]);                \
                af[mi][2] = U32(&As[buf][rbase + g][kk + 2*tg + 8]);                \
                af[mi][3] = U32(&As[buf][rbase + g + 8][kk + 2*tg + 8]);            \
            }                                                                       \
            _Pragma("unroll")                                                       \
            for (int ni = 0; ni < 4; ni++) {                                        \
                const int cbase = wn + ni * 8;                                      \
                bf[ni][0] = U32(&Bs[buf][cbase + g][kk + 2*tg]);                    \
                bf[ni][1] = U32(&Bs[buf][cbase + g][kk + 2*tg + 8]);                \
            }                                                                       \
            _Pragma("unroll")                                                       \
            for (int mi = 0; mi < 4; mi++)                                          \
                _Pragma("unroll")                                                   \
                for (int ni = 0; ni < 4; ni++)                                      \
                    mma_f16(acc[mi][ni], af[mi], bf[ni]);                           \
        }                                                                           \
        __syncthreads();                                                            \
    }

// ---------------------------------------------------------------------------
// Kernel 1: QKV GEMM + bias + RoPE -> g_Q (scaled), g_K, g_Vt (transposed)
// ---------------------------------------------------------------------------
__global__ __launch_bounds__(256) void qkv_gemm_kernel(
    const float* __restrict__ bias)
{
    GEMM_MAINLOOP(g_Xh, g_Wh)

    #pragma unroll
    for (int mi = 0; mi < 4; mi++) {
        #pragma unroll
        for (int ni = 0; ni < 4; ni++) {
            float4 c = acc[mi][ni];
            const int col = n0 + wn + ni * 8 + 2 * tg;   // even
            const int which = col >> 10;                 // 0=q,1=k,2=v
            const int cc = col & 1023;
            const int h = cc >> 6;
            const int d0 = cc & 63;
            const float b0 = bias[col], b1 = bias[col + 1];
            const float invf = exp2f(-(float)d0 * ROPE_L2);
            const int r0 = m0 + wm + mi * 16 + g;
            #pragma unroll
            for (int half_i = 0; half_i < 2; half_i++) {
                const int r = r0 + half_i * 8;
                float v0 = (half_i ? c.z : c.x) + b0;
                float v1 = (half_i ? c.w : c.y) + b1;
                const int b = r >> 11;
                const int t = r & (SEQ - 1);
                const int bh = b * NHEAD + h;
                if (which == 2) {
                    // transposed store: [bh][d][t]
                    const size_t vb = (size_t)bh * HDIM * SEQ;
                    g_Vt[vb + (size_t)d0 * SEQ + t]       = __float2half_rn(v0);
                    g_Vt[vb + (size_t)(d0 + 1) * SEQ + t] = __float2half_rn(v1);
                } else {
                    float s, co;
                    sincosf((float)t * invf, &s, &co);
                    float r0v = v0 * co - v1 * s;
                    float r1v = v0 * s  + v1 * co;
                    const size_t base = ((size_t)bh * SEQ + t) * HDIM + d0;
                    if (which == 0) {  // pre-scale Q by 1/sqrt(64)
                        *(uint32_t*)&g_Q[base] = packh2(r0v * 0.125f, r1v * 0.125f);
                    } else {
                        *(uint32_t*)&g_K[base] = packh2(r0v, r1v);
                    }
                }
            }
        }
    }
}

// ---------------------------------------------------------------------------
// Kernel 2: causal flash attention, fp16 m16n8k16 mma.
// 128 threads (4 warps); Br=64 (16 rows/warp), Bc=32, double-buffered cp.async.
// S C-fragment reused directly as P A-fragment (no shuffles).
// V staged from transposed layout so P*V B-frags are contiguous f16x2.
// ---------------------------------------------------------------------------
__global__ __launch_bounds__(128, 4) void attn_kernel()
{
    __shared__ __half Ks[2][32][KSPAD];   // [buf][key][dim]
    __shared__ __half Vs[2][64][VSPAD];   // [buf][dim][key]

    const int tid = threadIdx.x;
    const int w = tid >> 5, lane = tid & 31, g = lane >> 2, tg = lane & 3;
    const int wq0 = w * 16;
    const int bh = blockIdx.y;
    const int q0 = ((int)gridDim.x - 1 - (int)blockIdx.x) * 64;  // heavy blocks first
    const size_t kqbase = (size_t)bh * SEQ * HDIM;   // Q/K base
    const size_t vbase  = (size_t)bh * HDIM * SEQ;   // Vt base
    const int lr0 = wq0 + g, lr1 = wq0 + g + 8;

    // K: 32 rows x 64 halves; V: 64 rows x 32 halves. 2 cp16 each per thread.
#define ATTN_STAGE(B, S0)                                                          \
    {                                                                              \
        const int kr = tid >> 2, kc = (tid & 3) * 16;                              \
        cp16(&Ks[B][kr][kc],     g_K + kqbase + (size_t)((S0) + kr) * HDIM + kc);  \
        cp16(&Ks[B][kr][kc + 8], g_K + kqbase + (size_t)((S0) + kr) * HDIM + kc + 8);\
        const int vr = tid >> 1, vc = (tid & 1) * 16;                              \
        cp16(&Vs[B][vr][vc],     g_Vt + vbase + (size_t)vr * SEQ + (S0) + vc);     \
        cp16(&Vs[B][vr][vc + 8], g_Vt + vbase + (size_t)vr * SEQ + (S0) + vc + 8); \
        CP_COMMIT;                                                                 \
    }

    const int ntiles = q0 / 32 + 2;
    ATTN_STAGE(0, 0)
    ATTN_STAGE(1, 32)

    // Q fragments straight from gmem (fp16, pre-scaled)
    uint32_t qf[4][4];
    {
        const __half* qb = g_Q + kqbase + (size_t)q0 * HDIM;
        #pragma unroll
        for (int ks = 0; ks < 4; ks++) {
            const int kk = ks * 16;
            qf[ks][0] = U32(qb + (size_t)lr0 * HDIM + kk + 2*tg);
            qf[ks][1] = U32(qb + (size_t)lr1 * HDIM + kk + 2*tg);
            qf[ks][2] = U32(qb + (size_t)lr0 * HDIM + kk + 2*tg + 8);
            qf[ks][3] = U32(qb + (size_t)lr1 * HDIM + kk + 2*tg + 8);
        }
    }

    float4 o[8];
    #pragma unroll
    for (int ni = 0; ni < 8; ni++) o[ni] = make_float4(0.f, 0.f, 0.f, 0.f);
    float m0r = -1e30f, m1r = -1e30f, l0 = 0.f, l1 = 0.f;

    for (int it = 0; it < ntiles; it++) {
        const int s0 = it * 32;
        if (it + 1 < ntiles) { CP_WAIT1; } else { CP_WAIT0; }
        __syncthreads();
        const int b = it & 1;

        // ---- S = Q * K^T (64 warp rows x 32 keys) ----
        float4 s[4];
        #pragma unroll
        for (int ni = 0; ni < 4; ni++) s[ni] = make_float4(0.f, 0.f, 0.f, 0.f);
        #pragma unroll
        for (int ks = 0; ks < 4; ks++) {
            const int kk = ks * 16;
            #pragma unroll
            for (int ni = 0; ni < 4; ni++) {
                uint32_t bfr[2];
                bfr[0] = U32(&Ks[b][ni * 8 + g][kk + 2*tg]);
                bfr[1] = U32(&Ks[b][ni * 8 + g][kk + 2*tg + 8]);
                mma_f16(s[ni], qf[ks], bfr);
            }
        }

        // ---- causal mask (only tiles that can cross the diagonal) ----
        if (s0 + 31 > q0) {
            #pragma unroll
            for (int ni = 0; ni < 4; ni++) {
                const int c0 = s0 + ni * 8 + 2 * tg, c1 = c0 + 1;
                const int t0 = q0 + lr0, t1 = q0 + lr1;
                if (c0 > t0) s[ni].x = -1e30f;
                if (c1 > t0) s[ni].y = -1e30f;
                if (c0 > t1) s[ni].z = -1e30f;
                if (c1 > t1) s[ni].w = -1e30f;
            }
        }

        // ---- online softmax ----
        float tm0 = -1e30f, tm1 = -1e30f;
        #pragma unroll
        for (int ni = 0; ni < 4; ni++) {
            tm0 = fmaxf(tm0, fmaxf(s[ni].x, s[ni].y));
            tm1 = fmaxf(tm1, fmaxf(s[ni].z, s[ni].w));
        }
        tm0 = fmaxf(tm0, __shfl_xor_sync(0xffffffffu, tm0, 1));
        tm0 = fmaxf(tm0, __shfl_xor_sync(0xffffffffu, tm0, 2));
        tm1 = fmaxf(tm1, __shfl_xor_sync(0xffffffffu, tm1, 1));
        tm1 = fmaxf(tm1, __shfl_xor_sync(0xffffffffu, tm1, 2));

        const float mn0 = fmaxf(m0r, tm0), mn1 = fmaxf(m1r, tm1);
        const float cr0 = __expf(m0r - mn0), cr1 = __expf(m1r - mn1);
        m0r = mn0; m1r = mn1;

        float ls0 = 0.f, ls1 = 0.f;
        #pragma unroll
        for (int ni = 0; ni < 4; ni++) {
            s[ni].x = __expf(s[ni].x - mn0);
            s[ni].y = __expf(s[ni].y - mn0);
            s[ni].z = __expf(s[ni].z - mn1);
            s[ni].w = __expf(s[ni].w - mn1);
            ls0 += s[ni].x + s[ni].y;
            ls1 += s[ni].z + s[ni].w;
        }
        ls0 += __shfl_xor_sync(0xffffffffu, ls0, 1);
        ls0 += __shfl_xor_sync(0xffffffffu, ls0, 2);
        ls1 += __shfl_xor_sync(0xffffffffu, ls1, 1);
        ls1 += __shfl_xor_sync(0xffffffffu, ls1, 2);
        l0 = l0 * cr0 + ls0;
        l1 = l1 * cr1 + ls1;

        #pragma unroll
        for (int ni = 0; ni < 8; ni++) {
            o[ni].x *= cr0; o[ni].y *= cr0;
            o[ni].z *= cr1; o[ni].w *= cr1;
        }

        // ---- O += P * V : S C-frag IS the P A-frag (fp16 pack, no shuffles) ----
        #pragma unroll
        for (int ks2 = 0; ks2 < 2; ks2++) {
            uint32_t af[4];
            af[0] = packh2(s[2*ks2].x,     s[2*ks2].y);
            af[1] = packh2(s[2*ks2].z,     s[2*ks2].w);
            af[2] = packh2(s[2*ks2 + 1].x, s[2*ks2 + 1].y);
            af[3] = packh2(s[2*ks2 + 1].z, s[2*ks2 + 1].w);
            const int kk = ks2 * 16;
            #pragma unroll
            for (int ni = 0; ni < 8; ni++) {
                uint32_t bfr[2];
                bfr[0] = U32(&Vs[b][ni * 8 + g][kk + 2*tg]);
                bfr[1] = U32(&Vs[b][ni * 8 + g][kk + 2*tg + 8]);
                mma_f16(o[ni], af, bfr);
            }
        }

        __syncthreads();
        if (it + 2 < ntiles) ATTN_STAGE(it & 1, s0 + 64)
    }

    // ---- epilogue: normalize, write fp16 g_A ----
    const float inv0 = 1.f / l0, inv1 = 1.f / l1;
    const int b2 = bh >> 4, h = bh & 15;
    const int t0 = q0 + lr0, t1 = q0 + lr1;
    __half* d0p = g_A + ((size_t)(b2 * SEQ + t0)) * CMODEL + h * HDIM;
    __half* d1p = g_A + ((size_t)(b2 * SEQ + t1)) * CMODEL + h * HDIM;
    #pragma unroll
    for (int ni = 0; ni < 8; ni++) {
        const int c0 = ni * 8 + 2 * tg;
        *(uint32_t*)&d0p[c0] = packh2(o[ni].x * inv0, o[ni].y * inv0);
        *(uint32_t*)&d1p[c0] = packh2(o[ni].z * inv1, o[ni].w * inv1);
    }
#undef ATTN_STAGE
}

// ---------------------------------------------------------------------------
// Kernel 3: output projection + bias -> d_out (fp32)
// ---------------------------------------------------------------------------
__global__ __launch_bounds__(256) void proj_gemm_kernel(
    const float* __restrict__ bias, float* __restrict__ out)
{
    GEMM_MAINLOOP(g_A, g_Woh)

    #pragma unroll
    for (int mi = 0; mi < 4; mi++) {
        #pragma unroll
        for (int ni = 0; ni < 4; ni++) {
            float4 c = acc[mi][ni];
            const int col = n0 + wn + ni * 8 + 2 * tg;
            const float b0 = bias[col], b1 = bias[col + 1];
            const int r0 = m0 + wm + mi * 16 + g;
            out[(size_t)r0 * CMODEL + col]           = c.x + b0;
            out[(size_t)r0 * CMODEL + col + 1]       = c.y + b1;
            out[(size_t)(r0 + 8) * CMODEL + col]     = c.z + b0;
            out[(size_t)(r0 + 8) * CMODEL + col + 1] = c.w + b1;
        }
    }
}

// ---------------------------------------------------------------------------
extern "C" void kernel_launch(void* const* d_in, const int* in_sizes, int n_in,
                              void* d_out, int out_size)
{
    const float* x      = (const float*)d_in[0];
    const float* qkv_w  = (const float*)d_in[1];
    const float* qkv_b  = (const float*)d_in[2];
    const float* out_w  = (const float*)d_in[3];
    const float* out_b  = (const float*)d_in[4];
    float* out = (float*)d_out;

    __half* xh;  cudaGetSymbolAddress((void**)&xh,  g_Xh);
    __half* wh;  cudaGetSymbolAddress((void**)&wh,  g_Wh);
    __half* woh; cudaGetSymbolAddress((void**)&woh, g_Woh);

    // fp32 -> fp16 conversion of GEMM operands
    {
        const int n4x = MROWS * CMODEL / 4;          // 2097152
        const int n4q = 3 * CMODEL * CMODEL / 4;     // 786432
        const int n4o = CMODEL * CMODEL / 4;         // 262144
        cvt_half_kernel<<<(n4x + 255) / 256, 256>>>((const float4*)x, (uint2*)xh, n4x);
        cvt_half_kernel<<<(n4q + 255) / 256, 256>>>((const float4*)qkv_w, (uint2*)wh, n4q);
        cvt_half_kernel<<<(n4o + 255) / 256, 256>>>((const float4*)out_w, (uint2*)woh, n4o);
    }

    qkv_gemm_kernel<<<dim3(3*CMODEL/128, MROWS/128), 256>>>(qkv_b);
    attn_kernel<<<dim3(SEQ/64, BH), 128>>>();
    proj_gemm_kernel<<<dim3(CMODEL/128, MROWS/128), 256>>>(out_b, out);
}

// round 12
// speedup vs baseline: 2.0326x; 1.0641x over previous
#include <cuda_runtime.h>
#include <cuda_fp16.h>
#include <math.h>
#include <stdint.h>

// Problem constants
#define BATCH 4
#define SEQ   2048
#define CMODEL 1024
#define NHEAD 16
#define HDIM  64
#define BH    (BATCH*NHEAD)          // 64
#define MROWS (BATCH*SEQ)            // 8192

// Scratch (allocation-free rule: __device__ globals)
__device__ __half g_Q[(size_t)BH*SEQ*HDIM];    // [bh][t][d], pre-scaled by 1/8
__device__ __half g_K[(size_t)BH*SEQ*HDIM];    // [bh][t][d]
__device__ __half g_Vt[(size_t)BH*HDIM*SEQ];   // [bh][d][t]  (transposed)
__device__ __half g_A[(size_t)MROWS*CMODEL];   // attention out (proj input)
__device__ __half g_Xh[(size_t)MROWS*CMODEL];      // x in fp16
__device__ __half g_Wh[(size_t)3*CMODEL*CMODEL];   // qkv_w in fp16
__device__ __half g_Woh[(size_t)CMODEL*CMODEL];    // out_w in fp16

// log2(10000)/64
#define ROPE_L2 0.20762050593060493f

#define KPAD 40    // GEMM: halves per smem row (32 used + 8 pad); 80B row, 16B-aligned
#define KSPAD 72   // attn K tile: 64 + 8 -> 144B row
#define VSPAD 40   // attn V tile: 32 + 8 -> 80B row

__device__ __forceinline__ void cp16(void* s, const void* g) {
    uint32_t sa = (uint32_t)__cvta_generic_to_shared(s);
    asm volatile("cp.async.cg.shared.global [%0], [%1], 16;\n" :: "r"(sa), "l"(g));
}
#define CP_COMMIT asm volatile("cp.async.commit_group;\n" ::: "memory")
#define CP_WAIT0  asm volatile("cp.async.wait_group 0;\n" ::: "memory")
#define CP_WAIT1  asm volatile("cp.async.wait_group 1;\n" ::: "memory")

#define U32(p) (*(const uint32_t*)(p))

__device__ __forceinline__ uint32_t smem_u32(const void* p) {
    return (uint32_t)__cvta_generic_to_shared(p);
}

__device__ __forceinline__ uint32_t packh2(float lo, float hi) {
    __half2 h = __floats2half2_rn(lo, hi);
    return *(uint32_t*)&h;
}

__device__ __forceinline__ void mma_f16(float4& d, const uint32_t* a, const uint32_t* b) {
    asm volatile(
        "mma.sync.aligned.m16n8k16.row.col.f32.f16.f16.f32 "
        "{%0,%1,%2,%3}, {%4,%5,%6,%7}, {%8,%9}, {%0,%1,%2,%3};\n"
        : "+f"(d.x), "+f"(d.y), "+f"(d.z), "+f"(d.w)
        : "r"(a[0]), "r"(a[1]), "r"(a[2]), "r"(a[3]), "r"(b[0]), "r"(b[1]));
}

#define LDSM4(R, ADDR) \
    asm volatile("ldmatrix.sync.aligned.m8n8.x4.shared.b16 {%0,%1,%2,%3}, [%4];" \
        : "=r"((R)[0]), "=r"((R)[1]), "=r"((R)[2]), "=r"((R)[3]) : "r"(ADDR))

// ---------------------------------------------------------------------------
// Kernel 0: fp32 -> fp16 convert (vectorized)
// ---------------------------------------------------------------------------
__global__ __launch_bounds__(256) void cvt_half_kernel(
    const float4* __restrict__ in, uint2* __restrict__ outp, int n4)
{
    const int i = blockIdx.x * 256 + threadIdx.x;
    if (i < n4) {
        float4 v = in[i];
        uint2 o;
        o.x = packh2(v.x, v.y);
        o.y = packh2(v.z, v.w);
        outp[i] = o;
    }
}

// ---------------------------------------------------------------------------
// GEMM mainloop: C[128x128] tile of A[M][1024](half) * B[N][1024](half)^T.
// R10 structure (static smem, 2-stage cp.async, prefetch-before-wait,
// 2 barriers/tile, BK=32). Fragment loads via ldmatrix.x4.
// ---------------------------------------------------------------------------
#define AS_BUF_BYTES (128 * KPAD * 2)   // 10240
#define GEMM_MAINLOOP(APTR, BPTR)                                                   \
    __shared__ __half As[2][128][KPAD];                                             \
    __shared__ __half Bs[2][128][KPAD];                                             \
    const int tid = threadIdx.x;                                                    \
    const int w = tid >> 5, lane = tid & 31, g = lane >> 2, tg = lane & 3;          \
    const int wm = (w & 1) * 64, wn = (w >> 1) * 32;                                \
    const int m0 = blockIdx.y * 128, n0 = blockIdx.x * 128;                         \
    const int lr = tid >> 1, lc = (tid & 1) * 16;                                   \
    const __half* ga = (APTR) + (size_t)(m0 + lr) * CMODEL + lc;                    \
    const __half* gb = (BPTR) + (size_t)(n0 + lr) * CMODEL + lc;                    \
    /* ldmatrix per-lane source addresses (stage 0) */                              \
    const int arow = wm + (lane & 15);                                              \
    const int akof = (lane & 16) >> 1;            /* 0 or 8 halves */               \
    const int brow = wn + (lane & 7) + ((lane & 16) >> 1);                          \
    const int bkof = lane & 8;                                                      \
    const uint32_t aaddr0 = smem_u32(&As[0][arow][akof]);                           \
    const uint32_t baddr0 = smem_u32(&Bs[0][brow][bkof]);                           \
    float4 acc[4][4];                                                               \
    _Pragma("unroll")                                                               \
    for (int i = 0; i < 4; i++)                                                     \
        _Pragma("unroll")                                                           \
        for (int j = 0; j < 4; j++) acc[i][j] = make_float4(0.f, 0.f, 0.f, 0.f);    \
    cp16(&As[0][lr][lc], ga); cp16(&As[0][lr][lc + 8], ga + 8);                     \
    cp16(&Bs[0][lr][lc], gb); cp16(&Bs[0][lr][lc + 8], gb + 8);                     \
    CP_COMMIT;                                                                      \
    for (int kt = 0; kt < 32; kt++) {                                               \
        if (kt < 31) {                                                              \
            const __half* pa = ga + (kt + 1) * 32;                                  \
            const __half* pb = gb + (kt + 1) * 32;                                  \
            __half* sa = &As[(kt + 1) & 1][lr][lc];                                 \
            __half* sb = &Bs[(kt + 1) & 1][lr][lc];                                 \
            cp16(sa, pa); cp16(sa + 8, pa + 8);                                     \
            cp16(sb, pb); cp16(sb + 8, pb + 8);                                     \
            CP_COMMIT; CP_WAIT1;                                                    \
        } else { CP_WAIT0; }                                                        \
        __syncthreads();                                                            \
        const uint32_t bofs = (uint32_t)(kt & 1) * AS_BUF_BYTES;                    \
        _Pragma("unroll")                                                           \
        for (int ks = 0; ks < 2; ks++) {                                            \
            const uint32_t kb = bofs + ks * 32;   /* 16 halves = 32B */             \
            uint32_t af[4][4], bt[2][4];                                            \
            _Pragma("unroll")                                                       \
            for (int mi = 0; mi < 4; mi++)                                          \
                LDSM4(af[mi], aaddr0 + kb + mi * (16 * KPAD * 2));                  \
            _Pragma("unroll")                                                       \
            for (int p = 0; p < 2; p++)                                             \
                LDSM4(bt[p], baddr0 + kb + p * (16 * KPAD * 2));                    \
            _Pragma("unroll")                                                       \
            for (int mi = 0; mi < 4; mi++)                                          \
                _Pragma("unroll")                                                   \
                for (int ni = 0; ni < 4; ni++)                                      \
                    mma_f16(acc[mi][ni], af[mi], &bt[ni >> 1][(ni & 1) * 2]);       \
        }                                                                           \
        __syncthreads();                                                            \
    }

// ---------------------------------------------------------------------------
// Kernel 1: QKV GEMM + bias + RoPE -> g_Q (scaled), g_K, g_Vt (transposed)
// ---------------------------------------------------------------------------
__global__ __launch_bounds__(256) void qkv_gemm_kernel(
    const float* __restrict__ bias)
{
    GEMM_MAINLOOP(g_Xh, g_Wh)

    #pragma unroll
    for (int mi = 0; mi < 4; mi++) {
        #pragma unroll
        for (int ni = 0; ni < 4; ni++) {
            float4 c = acc[mi][ni];
            const int col = n0 + wn + ni * 8 + 2 * tg;   // even
            const int which = col >> 10;                 // 0=q,1=k,2=v
            const int cc = col & 1023;
            const int h = cc >> 6;
            const int d0 = cc & 63;
            const float b0 = bias[col], b1 = bias[col + 1];
            const float invf = exp2f(-(float)d0 * ROPE_L2);
            const int r0 = m0 + wm + mi * 16 + g;
            #pragma unroll
            for (int half_i = 0; half_i < 2; half_i++) {
                const int r = r0 + half_i * 8;
                float v0 = (half_i ? c.z : c.x) + b0;
                float v1 = (half_i ? c.w : c.y) + b1;
                const int b = r >> 11;
                const int t = r & (SEQ - 1);
                const int bh = b * NHEAD + h;
                if (which == 2) {
                    const size_t vb = (size_t)bh * HDIM * SEQ;
                    g_Vt[vb + (size_t)d0 * SEQ + t]       = __float2half_rn(v0);
                    g_Vt[vb + (size_t)(d0 + 1) * SEQ + t] = __float2half_rn(v1);
                } else {
                    float s, co;
                    sincosf((float)t * invf, &s, &co);
                    float r0v = v0 * co - v1 * s;
                    float r1v = v0 * s  + v1 * co;
                    const size_t base = ((size_t)bh * SEQ + t) * HDIM + d0;
                    if (which == 0) {  // pre-scale Q by 1/sqrt(64)
                        *(uint32_t*)&g_Q[base] = packh2(r0v * 0.125f, r1v * 0.125f);
                    } else {
                        *(uint32_t*)&g_K[base] = packh2(r0v, r1v);
                    }
                }
            }
        }
    }
}

// ---------------------------------------------------------------------------
// Kernel 2: causal flash attention, fp16 m16n8k16 mma (R10 structure,
// fragment loads via ldmatrix.x4).
// ---------------------------------------------------------------------------
#define KS_BUF_BYTES (32 * KSPAD * 2)   // 4608
#define VS_BUF_BYTES (64 * VSPAD * 2)   // 5120

__global__ __launch_bounds__(128, 4) void attn_kernel()
{
    __shared__ __half Ks[2][32][KSPAD];   // [buf][key][dim]
    __shared__ __half Vs[2][64][VSPAD];   // [buf][dim][key]

    const int tid = threadIdx.x;
    const int w = tid >> 5, lane = tid & 31, g = lane >> 2, tg = lane & 3;
    const int wq0 = w * 16;
    const int bh = blockIdx.y;
    const int q0 = ((int)gridDim.x - 1 - (int)blockIdx.x) * 64;  // heavy blocks first
    const size_t kqbase = (size_t)bh * SEQ * HDIM;   // Q/K base
    const size_t vbase  = (size_t)bh * HDIM * SEQ;   // Vt base
    const int lr0 = wq0 + g, lr1 = wq0 + g + 8;

    // ldmatrix source addresses (B-fragment pattern, stage 0)
    const int xrow = (lane & 7) + ((lane & 16) >> 1);  // 0..15
    const int xkof = lane & 8;                          // 0 or 8
    const uint32_t kaddr0 = smem_u32(&Ks[0][xrow][xkof]);
    const uint32_t vaddr0 = smem_u32(&Vs[0][xrow][xkof]);

#define ATTN_STAGE(B, S0)                                                          \
    {                                                                              \
        const int kr = tid >> 2, kc = (tid & 3) * 16;                              \
        cp16(&Ks[B][kr][kc],     g_K + kqbase + (size_t)((S0) + kr) * HDIM + kc);  \
        cp16(&Ks[B][kr][kc + 8], g_K + kqbase + (size_t)((S0) + kr) * HDIM + kc + 8);\
        const int vr = tid >> 1, vc = (tid & 1) * 16;                              \
        cp16(&Vs[B][vr][vc],     g_Vt + vbase + (size_t)vr * SEQ + (S0) + vc);     \
        cp16(&Vs[B][vr][vc + 8], g_Vt + vbase + (size_t)vr * SEQ + (S0) + vc + 8); \
        CP_COMMIT;                                                                 \
    }

    const int ntiles = q0 / 32 + 2;
    ATTN_STAGE(0, 0)
    ATTN_STAGE(1, 32)

    // Q fragments straight from gmem (fp16, pre-scaled)
    uint32_t qf[4][4];
    {
        const __half* qb = g_Q + kqbase + (size_t)q0 * HDIM;
        #pragma unroll
        for (int ks = 0; ks < 4; ks++) {
            const int kk = ks * 16;
            qf[ks][0] = U32(qb + (size_t)lr0 * HDIM + kk + 2*tg);
            qf[ks][1] = U32(qb + (size_t)lr1 * HDIM + kk + 2*tg);
            qf[ks][2] = U32(qb + (size_t)lr0 * HDIM + kk + 2*tg + 8);
            qf[ks][3] = U32(qb + (size_t)lr1 * HDIM + kk + 2*tg + 8);
        }
    }

    float4 o[8];
    #pragma unroll
    for (int ni = 0; ni < 8; ni++) o[ni] = make_float4(0.f, 0.f, 0.f, 0.f);
    float m0r = -1e30f, m1r = -1e30f, l0 = 0.f, l1 = 0.f;

    for (int it = 0; it < ntiles; it++) {
        const int s0 = it * 32;
        if (it + 1 < ntiles) { CP_WAIT1; } else { CP_WAIT0; }
        __syncthreads();
        const uint32_t kbuf = (uint32_t)(it & 1) * KS_BUF_BYTES;
        const uint32_t vbuf = (uint32_t)(it & 1) * VS_BUF_BYTES;
        const int b = it & 1;
        (void)b;

        // ---- S = Q * K^T (64 warp rows x 32 keys) ----
        float4 s[4];
        #pragma unroll
        for (int ni = 0; ni < 4; ni++) s[ni] = make_float4(0.f, 0.f, 0.f, 0.f);
        #pragma unroll
        for (int ks = 0; ks < 4; ks++) {
            const uint32_t kb = kbuf + ks * 32;   // 16 halves
            uint32_t kt2[2][4];
            #pragma unroll
            for (int p = 0; p < 2; p++)
                LDSM4(kt2[p], kaddr0 + kb + p * (16 * KSPAD * 2));
            #pragma unroll
            for (int ni = 0; ni < 4; ni++)
                mma_f16(s[ni], qf[ks], &kt2[ni >> 1][(ni & 1) * 2]);
        }

        // ---- causal mask (only tiles that can cross the diagonal) ----
        if (s0 + 31 > q0) {
            #pragma unroll
            for (int ni = 0; ni < 4; ni++) {
                const int c0 = s0 + ni * 8 + 2 * tg, c1 = c0 + 1;
                const int t0 = q0 + lr0, t1 = q0 + lr1;
                if (c0 > t0) s[ni].x = -1e30f;
                if (c1 > t0) s[ni].y = -1e30f;
                if (c0 > t1) s[ni].z = -1e30f;
                if (c1 > t1) s[ni].w = -1e30f;
            }
        }

        // ---- online softmax ----
        float tm0 = -1e30f, tm1 = -1e30f;
        #pragma unroll
        for (int ni = 0; ni < 4; ni++) {
            tm0 = fmaxf(tm0, fmaxf(s[ni].x, s[ni].y));
            tm1 = fmaxf(tm1, fmaxf(s[ni].z, s[ni].w));
        }
        tm0 = fmaxf(tm0, __shfl_xor_sync(0xffffffffu, tm0, 1));
        tm0 = fmaxf(tm0, __shfl_xor_sync(0xffffffffu, tm0, 2));
        tm1 = fmaxf(tm1, __shfl_xor_sync(0xffffffffu, tm1, 1));
        tm1 = fmaxf(tm1, __shfl_xor_sync(0xffffffffu, tm1, 2));

        const float mn0 = fmaxf(m0r, tm0), mn1 = fmaxf(m1r, tm1);
        const float cr0 = __expf(m0r - mn0), cr1 = __expf(m1r - mn1);
        m0r = mn0; m1r = mn1;

        float ls0 = 0.f, ls1 = 0.f;
        #pragma unroll
        for (int ni = 0; ni < 4; ni++) {
            s[ni].x = __expf(s[ni].x - mn0);
            s[ni].y = __expf(s[ni].y - mn0);
            s[ni].z = __expf(s[ni].z - mn1);
            s[ni].w = __expf(s[ni].w - mn1);
            ls0 += s[ni].x + s[ni].y;
            ls1 += s[ni].z + s[ni].w;
        }
        ls0 += __shfl_xor_sync(0xffffffffu, ls0, 1);
        ls0 += __shfl_xor_sync(0xffffffffu, ls0, 2);
        ls1 += __shfl_xor_sync(0xffffffffu, ls1, 1);
        ls1 += __shfl_xor_sync(0xffffffffu, ls1, 2);
        l0 = l0 * cr0 + ls0;
        l1 = l1 * cr1 + ls1;

        #pragma unroll
        for (int ni = 0; ni < 8; ni++) {
            o[ni].x *= cr0; o[ni].y *= cr0;
            o[ni].z *= cr1; o[ni].w *= cr1;
        }

        // ---- O += P * V : S C-frag IS the P A-frag (fp16 pack) ----
        #pragma unroll
        for (int ks2 = 0; ks2 < 2; ks2++) {
            uint32_t af[4];
            af[0] = packh2(s[2*ks2].x,     s[2*ks2].y);
            af[1] = packh2(s[2*ks2].z,     s[2*ks2].w);
            af[2] = packh2(s[2*ks2 + 1].x, s[2*ks2 + 1].y);
            af[3] = packh2(s[2*ks2 + 1].z, s[2*ks2 + 1].w);
            const uint32_t kb = vbuf + ks2 * 32;   // 16 halves
            #pragma unroll
            for (int p = 0; p < 4; p++) {
                uint32_t vt[4];
                LDSM4(vt, vaddr0 + kb + p * (16 * VSPAD * 2));
                mma_f16(o[2*p],     af, &vt[0]);
                mma_f16(o[2*p + 1], af, &vt[2]);
            }
        }

        __syncthreads();
        if (it + 2 < ntiles) ATTN_STAGE(it & 1, s0 + 64)
    }

    // ---- epilogue: normalize, write fp16 g_A ----
    const float inv0 = 1.f / l0, inv1 = 1.f / l1;
    const int b2 = bh >> 4, h = bh & 15;
    const int t0 = q0 + lr0, t1 = q0 + lr1;
    __half* d0p = g_A + ((size_t)(b2 * SEQ + t0)) * CMODEL + h * HDIM;
    __half* d1p = g_A + ((size_t)(b2 * SEQ + t1)) * CMODEL + h * HDIM;
    #pragma unroll
    for (int ni = 0; ni < 8; ni++) {
        const int c0 = ni * 8 + 2 * tg;
        *(uint32_t*)&d0p[c0] = packh2(o[ni].x * inv0, o[ni].y * inv0);
        *(uint32_t*)&d1p[c0] = packh2(o[ni].z * inv1, o[ni].w * inv1);
    }
#undef ATTN_STAGE
}

// ---------------------------------------------------------------------------
// Kernel 3: output projection + bias -> d_out (fp32)
// ---------------------------------------------------------------------------
__global__ __launch_bounds__(256) void proj_gemm_kernel(
    const float* __restrict__ bias, float* __restrict__ out)
{
    GEMM_MAINLOOP(g_A, g_Woh)

    #pragma unroll
    for (int mi = 0; mi < 4; mi++) {
        #pragma unroll
        for (int ni = 0; ni < 4; ni++) {
            float4 c = acc[mi][ni];
            const int col = n0 + wn + ni * 8 + 2 * tg;
            const float b0 = bias[col], b1 = bias[col + 1];
            const int r0 = m0 + wm + mi * 16 + g;
            out[(size_t)r0 * CMODEL + col]           = c.x + b0;
            out[(size_t)r0 * CMODEL + col + 1]       = c.y + b1;
            out[(size_t)(r0 + 8) * CMODEL + col]     = c.z + b0;
            out[(size_t)(r0 + 8) * CMODEL + col + 1] = c.w + b1;
        }
    }
}

// ---------------------------------------------------------------------------
extern "C" void kernel_launch(void* const* d_in, const int* in_sizes, int n_in,
                              void* d_out, int out_size)
{
    const float* x      = (const float*)d_in[0];
    const float* qkv_w  = (const float*)d_in[1];
    const float* qkv_b  = (const float*)d_in[2];
    const float* out_w  = (const float*)d_in[3];
    const float* out_b  = (const float*)d_in[4];
    float* out = (float*)d_out;

    __half* xh;  cudaGetSymbolAddress((void**)&xh,  g_Xh);
    __half* wh;  cudaGetSymbolAddress((void**)&wh,  g_Wh);
    __half* woh; cudaGetSymbolAddress((void**)&woh, g_Woh);

    // fp32 -> fp16 conversion of GEMM operands
    {
        const int n4x = MROWS * CMODEL / 4;          // 2097152
        const int n4q = 3 * CMODEL * CMODEL / 4;     // 786432
        const int n4o = CMODEL * CMODEL / 4;         // 262144
        cvt_half_kernel<<<(n4x + 255) / 256, 256>>>((const float4*)x, (uint2*)xh, n4x);
        cvt_half_kernel<<<(n4q + 255) / 256, 256>>>((const float4*)qkv_w, (uint2*)wh, n4q);
        cvt_half_kernel<<<(n4o + 255) / 256, 256>>>((const float4*)out_w, (uint2*)woh, n4o);
    }

    qkv_gemm_kernel<<<dim3(3*CMODEL/128, MROWS/128), 256>>>(qkv_b);
    attn_kernel<<<dim3(SEQ/64, BH), 128>>>();
    proj_gemm_kernel<<<dim3(CMODEL/128, MROWS/128), 256>>>(out_b, out);
}